// round 2
// baseline (speedup 1.0000x reference)
#include <cuda_runtime.h>
#include <cstdint>

#define S_LEN 128
#define B_SZ  64
#define V_SZ  32000
#define E_SZ  32
#define H_SZ  16
#define NROWS (S_LEN * B_SZ)   // 8192

// Scratch (allocation-free rule: __device__ globals)
__device__ float g_xin[NROWS * H_SZ];  // x @ Wx, precomputed per (s,b)
__device__ float g_h[NROWS * H_SZ];    // hidden states after recurrence

// ---------------- f32x2 helpers -------------------------------------------------
__device__ __forceinline__ unsigned long long pk2(float lo, float hi) {
    unsigned long long r;
    asm("mov.b64 %0, {%1, %2};" : "=l"(r) : "f"(lo), "f"(hi));
    return r;
}
__device__ __forceinline__ unsigned long long fma2(unsigned long long a,
                                                   unsigned long long b,
                                                   unsigned long long c) {
    unsigned long long d;
    asm("fma.rn.f32x2 %0, %1, %2, %3;" : "=l"(d) : "l"(a), "l"(b), "l"(c));
    return d;
}
__device__ __forceinline__ float2 upk2(unsigned long long a) {
    float2 r;
    asm("mov.b64 {%0, %1}, %2;" : "=f"(r.x), "=f"(r.y) : "l"(a));
    return r;
}
__device__ __forceinline__ uint32_t s2u(const void* p) {
    uint32_t a;
    asm("{ .reg .u64 t; cvta.to.shared.u64 t, %1; cvt.u32.u64 %0, t; }"
        : "=r"(a) : "l"(p));
    return a;
}

// ---------------- K0: xin[s,b,:] = lookup[idx[s,b],:] @ Wx ----------------------
__global__ void k_embed(const int* __restrict__ idx,
                        const float* __restrict__ lookup,
                        const float* __restrict__ wx) {
    int t = blockIdx.x * blockDim.x + threadIdx.x;  // t = row*16 + j
    int row = t >> 4;
    int j   = t & 15;
    int tok = idx[row];
    const float* L = lookup + (long)tok * E_SZ;
    float acc = 0.f;
#pragma unroll
    for (int e = 0; e < E_SZ; e++) acc += L[e] * wx[e * H_SZ + j];
    g_xin[t] = acc;
}

// ---------------- K1: sequential Elman recurrence (1 block, 1024 threads) -------
__global__ void k_recur(const float* __restrict__ wh,
                        const float* __restrict__ h0) {
    __shared__ float hs[B_SZ * H_SZ];    // current hidden state [b][j]
    __shared__ float whs[H_SZ * H_SZ];   // Wh [k][j]
    int t = threadIdx.x;                 // t = b*16 + j
    int b = t >> 4;
    int j = t & 15;
    if (t < H_SZ * H_SZ) whs[t] = wh[t];
    hs[t] = h0[t];
    __syncthreads();

    float xin = g_xin[t];
    for (int s = 0; s < S_LEN; s++) {
        float nxt = 0.f;
        if (s + 1 < S_LEN) nxt = g_xin[(s + 1) * (B_SZ * H_SZ) + t];
        float acc = xin;
#pragma unroll
        for (int k = 0; k < H_SZ; k++) acc += hs[b * H_SZ + k] * whs[k * H_SZ + j];
        float nh = tanhf(acc);
        __syncthreads();
        hs[t] = nh;
        g_h[s * (B_SZ * H_SZ) + t] = nh;
        xin = nxt;
        __syncthreads();
    }
}

// ---------------- K2: fused logits GEMM + log_softmax (col-pair f32x2) ----------
// Block: 256 threads, 8 warps; warp owns 2 rows (all V). Chunk VC=256 cols staged
// in double-buffered smem via cp.async. Lane covers cols [4l,4l+3] and
// [128+4l, 128+4l+3] -> W column-pairs read straight from smem as 64-bit values,
// h broadcast pairs {h,h} precomputed ONCE in registers. Inner k-step:
// 2x LDS.128 + 8x FFMA2, zero MOVs.
#define VC     256
#define RPW    2
#define RPB    16                   // 8 warps * 2 rows
#define NBLK   (NROWS / RPB)        // 512
#define CHUNKS (V_SZ / VC)          // 125

__device__ __forceinline__ void stage_chunk(uint32_t sbase, int buf,
                                            const float* __restrict__ wo,
                                            int tid, int vc) {
    // chunk = 16 k-rows x 256 floats = 1024 16B units; 4 units per thread
#pragma unroll
    for (int i = 0; i < 4; i++) {
        int uu = tid + i * 256;
        int k  = uu >> 6;            // 64 units per k-row
        int c4 = (uu & 63) * 4;
        uint32_t dst = sbase + (uint32_t)(buf * (H_SZ * VC * 4) + (k * VC + c4) * 4);
        const float* src = wo + (long)k * V_SZ + vc + c4;
        asm volatile("cp.async.cg.shared.global [%0], [%1], 16;\n"
                     :: "r"(dst), "l"(src));
    }
    asm volatile("cp.async.commit_group;\n");
}

__global__ __launch_bounds__(256, 2)
void k_logsoftmax(const float* __restrict__ wo, float* __restrict__ out) {
    __shared__ float ws[2][H_SZ][VC];  // 2 x 16KB
    int tid  = threadIdx.x;
    int warp = tid >> 5;
    int lane = tid & 31;
    int row0 = blockIdx.x * RPB + warp * RPW;

    // h broadcast pairs {h,h}: built once, reused for all 250 chunk iterations
    unsigned long long hp[RPW][H_SZ];
#pragma unroll
    for (int k = 0; k < H_SZ; k++) {
        float ha = g_h[(row0 + 0) * H_SZ + k];
        float hb = g_h[(row0 + 1) * H_SZ + k];
        hp[0][k] = pk2(ha, ha);
        hp[1][k] = pk2(hb, hb);
    }

    uint32_t sbase = s2u(ws);
    stage_chunk(sbase, 0, wo, tid, 0);

    float psum0 = 0.f, psum1 = 0.f;
    float lse0 = 0.f, lse1 = 0.f;

    for (int idx = 0; idx < 2 * CHUNKS; idx++) {
        int buf = idx & 1;
        int ci  = (idx < CHUNKS) ? idx : idx - CHUNKS;
        int vc  = ci * VC;

        if (idx + 1 < 2 * CHUNKS) {
            int ni  = idx + 1;
            int nci = (ni < CHUNKS) ? ni : ni - CHUNKS;
            stage_chunk(sbase, buf ^ 1, wo, tid, nci * VC);
            asm volatile("cp.async.wait_group 1;\n");
        } else {
            asm volatile("cp.async.wait_group 0;\n");
        }
        __syncthreads();

        unsigned long long acc[RPW][4];
#pragma unroll
        for (int c = 0; c < 4; c++) { acc[0][c] = 0ULL; acc[1][c] = 0ULL; }

#pragma unroll
        for (int k = 0; k < H_SZ; k++) {
            ulonglong2 wA = *reinterpret_cast<const ulonglong2*>(&ws[buf][k][4 * lane]);
            ulonglong2 wB = *reinterpret_cast<const ulonglong2*>(&ws[buf][k][128 + 4 * lane]);
            acc[0][0] = fma2(hp[0][k], wA.x, acc[0][0]);
            acc[1][0] = fma2(hp[1][k], wA.x, acc[1][0]);
            acc[0][1] = fma2(hp[0][k], wA.y, acc[0][1]);
            acc[1][1] = fma2(hp[1][k], wA.y, acc[1][1]);
            acc[0][2] = fma2(hp[0][k], wB.x, acc[0][2]);
            acc[1][2] = fma2(hp[1][k], wB.x, acc[1][2]);
            acc[0][3] = fma2(hp[0][k], wB.y, acc[0][3]);
            acc[1][3] = fma2(hp[1][k], wB.y, acc[1][3]);
        }

        if (idx < CHUNKS) {
            // pass 0: accumulate sum(exp(logit)); logits are O(1), no max needed
#pragma unroll
            for (int c = 0; c < 4; c++) {
                float2 p0 = upk2(acc[0][c]);
                float2 p1 = upk2(acc[1][c]);
                psum0 += __expf(p0.x); psum0 += __expf(p0.y);
                psum1 += __expf(p1.x); psum1 += __expf(p1.y);
            }
            if (ci == CHUNKS - 1) {
                // rows are warp-private: warp shuffle reduce
                float s0 = psum0, s1 = psum1;
#pragma unroll
                for (int o = 16; o > 0; o >>= 1) {
                    s0 += __shfl_xor_sync(0xffffffffu, s0, o);
                    s1 += __shfl_xor_sync(0xffffffffu, s1, o);
                }
                lse0 = logf(s0);
                lse1 = logf(s1);
            }
        } else {
            // pass 1: recompute and store logit - lse
            float2 a0 = upk2(acc[0][0]), a1 = upk2(acc[0][1]);
            float2 a2 = upk2(acc[0][2]), a3 = upk2(acc[0][3]);
            float2 b0 = upk2(acc[1][0]), b1 = upk2(acc[1][1]);
            float2 b2 = upk2(acc[1][2]), b3 = upk2(acc[1][3]);
            float4 o0 = {a0.x - lse0, a0.y - lse0, a1.x - lse0, a1.y - lse0};
            float4 o1 = {a2.x - lse0, a2.y - lse0, a3.x - lse0, a3.y - lse0};
            float4 o2 = {b0.x - lse1, b0.y - lse1, b1.x - lse1, b1.y - lse1};
            float4 o3 = {b2.x - lse1, b2.y - lse1, b3.x - lse1, b3.y - lse1};
            long base0 = (long)(row0 + 0) * V_SZ + vc;
            long base1 = (long)(row0 + 1) * V_SZ + vc;
            *reinterpret_cast<float4*>(out + base0 + 4 * lane)       = o0;
            *reinterpret_cast<float4*>(out + base0 + 128 + 4 * lane) = o1;
            *reinterpret_cast<float4*>(out + base1 + 4 * lane)       = o2;
            *reinterpret_cast<float4*>(out + base1 + 128 + 4 * lane) = o3;
        }
        __syncthreads();
    }
}

// ---------------- launch --------------------------------------------------------
extern "C" void kernel_launch(void* const* d_in, const int* in_sizes, int n_in,
                              void* d_out, int out_size) {
    const int*   input_batch = (const int*)d_in[0];    // [S,B]
    const float* lookup      = (const float*)d_in[1];  // [V,E]
    const float* weight_x    = (const float*)d_in[2];  // [E,H]
    const float* weight_h    = (const float*)d_in[3];  // [H,H]
    const float* weight_o    = (const float*)d_in[4];  // [H,V]
    const float* h0          = (const float*)d_in[5];  // [B,H]
    float*       out         = (float*)d_out;          // [S,B,V]

    k_embed<<<(NROWS * H_SZ) / 256, 256>>>(input_batch, lookup, weight_x);
    k_recur<<<1, B_SZ * H_SZ>>>(weight_h, h0);
    k_logsoftmax<<<NBLK, 256>>>(weight_o, out);
}

// round 5
// speedup vs baseline: 1.2448x; 1.2448x over previous
#include <cuda_runtime.h>
#include <cuda_bf16.h>
#include <cstdint>

#define S_LEN 128
#define B_SZ  64
#define V_SZ  32000
#define E_SZ  32
#define H_SZ  16
#define NROWS (S_LEN * B_SZ)   // 8192

#define MT     128             // rows per CTA (8 warps x 16 rows)
#define NMT    (NROWS / MT)    // 64
#define VSPLIT 4
#define VR     (V_SZ / VSPLIT) // 8000 cols per CTA
#define NG     (VR / 16)       // 500 col-groups (16 cols each)

// -------- device scratch (allocation-free rule) --------------------------------
__device__ float    g_xin[NROWS * H_SZ];
__device__ float    g_h[NROWS * H_SZ];
__device__ uint32_t g_wt2[V_SZ * H_SZ / 2];     // Wo in MMA-B-fragment layout (bf16 pairs)
__device__ float    g_ps[NROWS * VSPLIT];       // partial sum(exp) per (row, vsplit)

// -------- helpers ---------------------------------------------------------------
__device__ __forceinline__ uint32_t packbf(float lo, float hi) {
    __nv_bfloat162 p = __floats2bfloat162_rn(lo, hi);
    return *reinterpret_cast<uint32_t*>(&p);
}

// D = A(16x16 bf16, row) * B(16x8 bf16, col) + 0, fp32 accum
__device__ __forceinline__ void mma16816(float d[4], const uint32_t a[4],
                                         uint32_t b0, uint32_t b1) {
    float z = 0.f;
    asm volatile(
        "mma.sync.aligned.m16n8k16.row.col.f32.bf16.bf16.f32 "
        "{%0,%1,%2,%3}, {%4,%5,%6,%7}, {%8,%9}, {%10,%11,%12,%13};"
        : "=f"(d[0]), "=f"(d[1]), "=f"(d[2]), "=f"(d[3])
        : "r"(a[0]), "r"(a[1]), "r"(a[2]), "r"(a[3]),
          "r"(b0), "r"(b1),
          "f"(z), "f"(z), "f"(z), "f"(z));
}

// -------- K0: xin = lookup[idx] @ Wx --------------------------------------------
__global__ void k_embed(const int* __restrict__ idx,
                        const float* __restrict__ lookup,
                        const float* __restrict__ wx) {
    int t = blockIdx.x * blockDim.x + threadIdx.x;
    int row = t >> 4, j = t & 15;
    const float* L = lookup + (long)idx[row] * E_SZ;
    float acc = 0.f;
#pragma unroll
    for (int e = 0; e < E_SZ; e++) acc += L[e] * wx[e * H_SZ + j];
    g_xin[t] = acc;
}

// -------- K1: sequential Elman recurrence (1 block, 1024 threads) ---------------
__global__ void k_recur(const float* __restrict__ wh, const float* __restrict__ h0) {
    __shared__ float hs[B_SZ * H_SZ];
    __shared__ float whs[H_SZ * H_SZ];
    int t = threadIdx.x, b = t >> 4, j = t & 15;
    if (t < H_SZ * H_SZ) whs[t] = wh[t];
    hs[t] = h0[t];
    __syncthreads();
    float xin = g_xin[t];
    for (int s = 0; s < S_LEN; s++) {
        float nxt = (s + 1 < S_LEN) ? g_xin[(s + 1) * (B_SZ * H_SZ) + t] : 0.f;
        float acc = xin;
#pragma unroll
        for (int k = 0; k < H_SZ; k++) acc += hs[b * H_SZ + k] * whs[k * H_SZ + j];
        float nh = tanhf(acc);
        __syncthreads();
        hs[t] = nh;
        g_h[s * (B_SZ * H_SZ) + t] = nh;
        xin = nxt;
        __syncthreads();
    }
}

// -------- K_wt: Wo [16,32000] f32 -> g_wt2 fragment-native bf16 layout ----------
// Group g covers cols [16g, 16g+16). u32 index t = g*128 + lane*4 + r,
// r = tile*2 + rr (tile: cols +0..7 / +8..15):
//   col = 16g + tile*8 + lane/4,  k0 = (lane%4)*2 + rr*8
//   value = bf16x2( Wo[k0][col], Wo[k0+1][col] )
// => warp LDG.128 at (g*128 + lane*4) yields {B_t0_r0, B_t0_r1, B_t1_r0, B_t1_r1}.
__global__ void k_wt(const float* __restrict__ wo) {
    int t = blockIdx.x * blockDim.x + threadIdx.x;   // 0 .. 255999
    int g = t >> 7, rem = t & 127;
    int lane = rem >> 2, r = rem & 3;
    int col = g * 16 + (r >> 1) * 8 + (lane >> 2);
    int k0  = (lane & 3) * 2 + (r & 1) * 8;
    g_wt2[t] = packbf(wo[k0 * V_SZ + col], wo[(k0 + 1) * V_SZ + col]);
}

// -------- K2: HMMA logits GEMM + log-softmax (pass0: sums, pass1: store) --------
__global__ __launch_bounds__(256, 2)
void k2(float* __restrict__ out, int pass) {
    int tid  = threadIdx.x;
    int w    = tid >> 5;
    int lane = tid & 31;
    int bx   = blockIdx.x;             // vocab split
    int m0   = blockIdx.y * MT;
    int wr0  = m0 + w * 16;            // warp's 16-row tile base
    int rA   = lane >> 2;              // fragment row within tile (0..7)
    int kc   = (lane & 3) * 2;

    // A fragment (loop-invariant): rows wr0+rA, wr0+rA+8, k pairs kc, kc+8
    const float* hA = g_h + (long)(wr0 + rA) * H_SZ;
    const float* hB = g_h + (long)(wr0 + rA + 8) * H_SZ;
    uint32_t a[4];
    a[0] = packbf(hA[kc], hA[kc + 1]);
    a[1] = packbf(hB[kc], hB[kc + 1]);
    a[2] = packbf(hA[kc + 8], hA[kc + 9]);
    a[3] = packbf(hB[kc + 8], hB[kc + 9]);

    float lseA = 0.f, lseB = 0.f;
    if (pass) {
        float4 p = *reinterpret_cast<const float4*>(g_ps + (long)(wr0 + rA) * VSPLIT);
        float4 q = *reinterpret_cast<const float4*>(g_ps + (long)(wr0 + rA + 8) * VSPLIT);
        lseA = logf(p.x + p.y + p.z + p.w);
        lseB = logf(q.x + q.y + q.z + q.w);
    }

    const uint4* bptr = reinterpret_cast<const uint4*>(g_wt2) + (long)bx * NG * 32 + lane;
    long orowA = (long)(wr0 + rA) * V_SZ;
    long orowB = orowA + 8L * V_SZ;
    int  cbase = bx * VR + kc;         // + g*16 (+8 for tile1)

    float psA = 0.f, psB = 0.f;

#pragma unroll 4
    for (int g = 0; g < NG; g++) {
        uint4 b = bptr[(long)g * 32];  // B frags for 16 cols (2 n-tiles)
        float d0[4], d1[4];
        mma16816(d0, a, b.x, b.y);
        mma16816(d1, a, b.z, b.w);
        if (pass == 0) {
            psA += __expf(d0[0]) + __expf(d0[1]) + __expf(d1[0]) + __expf(d1[1]);
            psB += __expf(d0[2]) + __expf(d0[3]) + __expf(d1[2]) + __expf(d1[3]);
        } else {
            int col = cbase + g * 16;
            float2 o;
            o.x = d0[0] - lseA; o.y = d0[1] - lseA;
            *reinterpret_cast<float2*>(out + orowA + col)     = o;
            o.x = d1[0] - lseA; o.y = d1[1] - lseA;
            *reinterpret_cast<float2*>(out + orowA + col + 8) = o;
            o.x = d0[2] - lseB; o.y = d0[3] - lseB;
            *reinterpret_cast<float2*>(out + orowB + col)     = o;
            o.x = d1[2] - lseB; o.y = d1[3] - lseB;
            *reinterpret_cast<float2*>(out + orowB + col + 8) = o;
        }
    }

    if (pass == 0) {
        // per-row partial sums: reduce across the 4 lanes of each quad
        psA += __shfl_xor_sync(0xffffffffu, psA, 1);
        psA += __shfl_xor_sync(0xffffffffu, psA, 2);
        psB += __shfl_xor_sync(0xffffffffu, psB, 1);
        psB += __shfl_xor_sync(0xffffffffu, psB, 2);
        if ((lane & 3) == 0) {
            g_ps[(long)(wr0 + rA) * VSPLIT + bx]     = psA;
            g_ps[(long)(wr0 + rA + 8) * VSPLIT + bx] = psB;
        }
    }
}

// -------- launch ----------------------------------------------------------------
extern "C" void kernel_launch(void* const* d_in, const int* in_sizes, int n_in,
                              void* d_out, int out_size) {
    const int*   input_batch = (const int*)d_in[0];
    const float* lookup      = (const float*)d_in[1];
    const float* weight_x    = (const float*)d_in[2];
    const float* weight_h    = (const float*)d_in[3];
    const float* weight_o    = (const float*)d_in[4];
    const float* h0          = (const float*)d_in[5];
    float*       out         = (float*)d_out;

    k_embed<<<(NROWS * H_SZ) / 256, 256>>>(input_batch, lookup, weight_x);
    k_wt<<<(V_SZ * H_SZ / 2) / 256, 256>>>(weight_o);
    k_recur<<<1, B_SZ * H_SZ>>>(weight_h, h0);
    dim3 g2(VSPLIT, NMT);
    k2<<<g2, 256>>>(out, 0);
    k2<<<g2, 256>>>(out, 1);
}

// round 7
// speedup vs baseline: 2.0290x; 1.6300x over previous
#include <cuda_runtime.h>
#include <cuda_bf16.h>
#include <cstdint>

#define S_LEN 128
#define B_SZ  64
#define V_SZ  32000
#define E_SZ  32
#define H_SZ  16
#define NROWS (S_LEN * B_SZ)   // 8192

#define MT     128             // rows per CTA (8 warps x 16 rows)
#define NMT    (NROWS / MT)    // 64
#define VSPLIT 16
#define VR     (V_SZ / VSPLIT) // 2000 cols per CTA
#define NG     (VR / 16)       // 125 col-groups (16 cols each)

// -------- device scratch (allocation-free rule) --------------------------------
__device__ float    g_xin[NROWS * H_SZ];
__device__ float    g_h[NROWS * H_SZ];
__device__ uint32_t g_wt2[V_SZ * H_SZ / 2];   // Wo in MMA-B-fragment layout
__device__ float    g_ps[NROWS * VSPLIT];     // partial sum(exp) per (row, vsplit)

// -------- helpers ---------------------------------------------------------------
__device__ __forceinline__ uint32_t packbf(float lo, float hi) {
    __nv_bfloat162 p = __floats2bfloat162_rn(lo, hi);
    return *reinterpret_cast<uint32_t*>(&p);
}

__device__ __forceinline__ void mma16816(float d[4], const uint32_t a[4],
                                         uint32_t b0, uint32_t b1) {
    float z = 0.f;
    asm volatile(
        "mma.sync.aligned.m16n8k16.row.col.f32.bf16.bf16.f32 "
        "{%0,%1,%2,%3}, {%4,%5,%6,%7}, {%8,%9}, {%10,%11,%12,%13};"
        : "=f"(d[0]), "=f"(d[1]), "=f"(d[2]), "=f"(d[3])
        : "r"(a[0]), "r"(a[1]), "r"(a[2]), "r"(a[3]),
          "r"(b0), "r"(b1),
          "f"(z), "f"(z), "f"(z), "f"(z));
}

// -------- K0: xin = lookup[idx] @ Wx --------------------------------------------
__global__ void k_embed(const int* __restrict__ idx,
                        const float* __restrict__ lookup,
                        const float* __restrict__ wx) {
    int t = blockIdx.x * blockDim.x + threadIdx.x;
    int row = t >> 4, j = t & 15;
    const float* L = lookup + (long)idx[row] * E_SZ;
    float acc = 0.f;
#pragma unroll
    for (int e = 0; e < E_SZ; e++) acc += L[e] * wx[e * H_SZ + j];
    g_xin[t] = acc;
}

// -------- K1: sequential Elman recurrence (1 block, 1024 threads) ---------------
__global__ void k_recur(const float* __restrict__ wh, const float* __restrict__ h0) {
    __shared__ float hs[B_SZ * H_SZ];
    __shared__ float whs[H_SZ * H_SZ];
    int t = threadIdx.x, b = t >> 4, j = t & 15;
    if (t < H_SZ * H_SZ) whs[t] = wh[t];
    hs[t] = h0[t];
    __syncthreads();
    float xin = g_xin[t];
    for (int s = 0; s < S_LEN; s++) {
        float nxt = (s + 1 < S_LEN) ? g_xin[(s + 1) * (B_SZ * H_SZ) + t] : 0.f;
        float acc = xin;
#pragma unroll
        for (int k = 0; k < H_SZ; k++) acc += hs[b * H_SZ + k] * whs[k * H_SZ + j];
        float nh = tanhf(acc);
        __syncthreads();
        hs[t] = nh;
        g_h[s * (B_SZ * H_SZ) + t] = nh;
        xin = nxt;
        __syncthreads();
    }
}

// -------- K_wt: Wo [16,32000] f32 -> g_wt2 fragment-native bf16 layout ----------
__global__ void k_wt(const float* __restrict__ wo) {
    int t = blockIdx.x * blockDim.x + threadIdx.x;
    int g = t >> 7, rem = t & 127;
    int lane = rem >> 2, r = rem & 3;
    int col = g * 16 + (r >> 1) * 8 + (lane >> 2);
    int k0  = (lane & 3) * 2 + (r & 1) * 8;
    g_wt2[t] = packbf(wo[k0 * V_SZ + col], wo[(k0 + 1) * V_SZ + col]);
}

// -------- K2: HMMA logits GEMM + log-softmax ------------------------------------
// grid = (VSPLIT, NMT) = 1024 CTAs, 256 thr. PASS 0: sum(exp); PASS 1: store.
template <int PASS>
__global__ __launch_bounds__(256)
void k2(float* __restrict__ out) {
    int tid  = threadIdx.x;
    int w    = tid >> 5;
    int lane = tid & 31;
    int lq   = lane & 3;               // quad lane
    int odd  = lq & 1;
    int bx   = blockIdx.x;             // vocab split
    int m0   = blockIdx.y * MT;
    int wr0  = m0 + w * 16;            // warp's 16-row tile base
    int rA   = lane >> 2;
    int kc   = lq * 2;

    // A fragment (loop-invariant)
    const float* hA = g_h + (long)(wr0 + rA) * H_SZ;
    const float* hB = g_h + (long)(wr0 + rA + 8) * H_SZ;
    uint32_t a[4];
    a[0] = packbf(hA[kc], hA[kc + 1]);
    a[1] = packbf(hB[kc], hB[kc + 1]);
    a[2] = packbf(hA[kc + 8], hA[kc + 9]);
    a[3] = packbf(hB[kc + 8], hB[kc + 9]);

    float lseA = 0.f, lseB = 0.f;
    if (PASS == 1) {
        const float4* pp = reinterpret_cast<const float4*>(g_ps + (long)(wr0 + rA) * VSPLIT);
        const float4* qq = reinterpret_cast<const float4*>(g_ps + (long)(wr0 + rA + 8) * VSPLIT);
        float sa = 0.f, sb = 0.f;
#pragma unroll
        for (int i = 0; i < VSPLIT / 4; i++) {
            float4 p = pp[i], q = qq[i];
            sa += (p.x + p.y) + (p.z + p.w);
            sb += (q.x + q.y) + (q.z + q.w);
        }
        lseA = logf(sa);
        lseB = logf(sb);
    }

    const uint4* bptr = reinterpret_cast<const uint4*>(g_wt2) + (long)bx * NG * 32 + lane;
    long orowA = (long)(wr0 + rA) * V_SZ;
    long orowB = orowA + 8L * V_SZ;
    int  vbase = bx * VR;
    int  cshift = 2 * lq + (odd ? 6 : 0);  // col offset of this thread's float4

    float psA = 0.f, psB = 0.f;

#pragma unroll 5
    for (int g = 0; g < NG; g++) {
        uint4 b = bptr[(long)g * 32];      // B frags for 16 cols (2 n-tiles)
        float d0[4], d1[4];
        mma16816(d0, a, b.x, b.y);
        mma16816(d1, a, b.z, b.w);
        if (PASS == 0) {
            psA += __expf(d0[0]) + __expf(d0[1]) + __expf(d1[0]) + __expf(d1[1]);
            psB += __expf(d0[2]) + __expf(d0[3]) + __expf(d1[2]) + __expf(d1[3]);
        } else {
            int col = vbase + g * 16 + cshift;
            // row A: build one float4 per thread via quad-pair exchange
            {
                float aA0 = d0[0] - lseA, aA1 = d0[1] - lseA;
                float aB0 = d1[0] - lseA, aB1 = d1[1] - lseA;
                float s0 = odd ? aA0 : aB0;
                float s1 = odd ? aA1 : aB1;
                float x0 = __shfl_xor_sync(0xffffffffu, s0, 1);
                float x1 = __shfl_xor_sync(0xffffffffu, s1, 1);
                float4 v;
                v.x = odd ? x0 : aA0;
                v.y = odd ? x1 : aA1;
                v.z = odd ? aB0 : x0;
                v.w = odd ? aB1 : x1;
                *reinterpret_cast<float4*>(out + orowA + col) = v;
            }
            // row B
            {
                float aA0 = d0[2] - lseB, aA1 = d0[3] - lseB;
                float aB0 = d1[2] - lseB, aB1 = d1[3] - lseB;
                float s0 = odd ? aA0 : aB0;
                float s1 = odd ? aA1 : aB1;
                float x0 = __shfl_xor_sync(0xffffffffu, s0, 1);
                float x1 = __shfl_xor_sync(0xffffffffu, s1, 1);
                float4 v;
                v.x = odd ? x0 : aA0;
                v.y = odd ? x1 : aA1;
                v.z = odd ? aB0 : x0;
                v.w = odd ? aB1 : x1;
                *reinterpret_cast<float4*>(out + orowB + col) = v;
            }
        }
    }

    if (PASS == 0) {
        psA += __shfl_xor_sync(0xffffffffu, psA, 1);
        psA += __shfl_xor_sync(0xffffffffu, psA, 2);
        psB += __shfl_xor_sync(0xffffffffu, psB, 1);
        psB += __shfl_xor_sync(0xffffffffu, psB, 2);
        if (lq == 0) {
            g_ps[(long)(wr0 + rA) * VSPLIT + bx]     = psA;
            g_ps[(long)(wr0 + rA + 8) * VSPLIT + bx] = psB;
        }
    }
}

// -------- launch ----------------------------------------------------------------
extern "C" void kernel_launch(void* const* d_in, const int* in_sizes, int n_in,
                              void* d_out, int out_size) {
    const int*   input_batch = (const int*)d_in[0];
    const float* lookup      = (const float*)d_in[1];
    const float* weight_x    = (const float*)d_in[2];
    const float* weight_h    = (const float*)d_in[3];
    const float* weight_o    = (const float*)d_in[4];
    const float* h0          = (const float*)d_in[5];
    float*       out         = (float*)d_out;

    k_embed<<<(NROWS * H_SZ) / 256, 256>>>(input_batch, lookup, weight_x);
    k_wt<<<(V_SZ * H_SZ / 2) / 256, 256>>>(weight_o);
    k_recur<<<1, B_SZ * H_SZ>>>(weight_h, h0);
    dim3 g2(VSPLIT, NMT);
    k2<0><<<g2, 256>>>(out);
    k2<1><<<g2, 256>>>(out);
}

// round 8
// speedup vs baseline: 2.2954x; 1.1313x over previous
#include <cuda_runtime.h>
#include <cuda_bf16.h>
#include <cstdint>

#define S_LEN 128
#define B_SZ  64
#define V_SZ  32000
#define E_SZ  32
#define H_SZ  16
#define NROWS (S_LEN * B_SZ)   // 8192

#define MT     128             // rows per CTA (8 warps x 16 rows)
#define NMT    (NROWS / MT)    // 64
#define VSPLIT 16
#define VR     (V_SZ / VSPLIT) // 2000 cols per CTA
#define NG     (VR / 16)       // 125 col-groups (16 cols each)

// -------- device scratch (allocation-free rule) --------------------------------
__device__ float    g_xin[NROWS * H_SZ];
__device__ float    g_h[NROWS * H_SZ];
__device__ uint32_t g_wt2[V_SZ * H_SZ / 2];   // Wo in MMA-B-fragment layout
__device__ float    g_ps[NROWS * VSPLIT];     // partial sum(exp) per (row, vsplit)

#define LOG2E 1.4426950408889634f

// -------- helpers ---------------------------------------------------------------
__device__ __forceinline__ uint32_t packbf(float lo, float hi) {
    __nv_bfloat162 p = __floats2bfloat162_rn(lo, hi);
    return *reinterpret_cast<uint32_t*>(&p);
}
__device__ __forceinline__ float ex2(float x) {
    float r;
    asm("ex2.approx.f32 %0, %1;" : "=f"(r) : "f"(x));
    return r;
}

__device__ __forceinline__ void mma16816(float d[4], const uint32_t a[4],
                                         uint32_t b0, uint32_t b1) {
    float z = 0.f;
    asm volatile(
        "mma.sync.aligned.m16n8k16.row.col.f32.bf16.bf16.f32 "
        "{%0,%1,%2,%3}, {%4,%5,%6,%7}, {%8,%9}, {%10,%11,%12,%13};"
        : "=f"(d[0]), "=f"(d[1]), "=f"(d[2]), "=f"(d[3])
        : "r"(a[0]), "r"(a[1]), "r"(a[2]), "r"(a[3]),
          "r"(b0), "r"(b1),
          "f"(z), "f"(z), "f"(z), "f"(z));
}

// -------- K0: xin = lookup[idx] @ Wx --------------------------------------------
__global__ void k_embed(const int* __restrict__ idx,
                        const float* __restrict__ lookup,
                        const float* __restrict__ wx) {
    int t = blockIdx.x * blockDim.x + threadIdx.x;
    int row = t >> 4, j = t & 15;
    const float* L = lookup + (long)idx[row] * E_SZ;
    float acc = 0.f;
#pragma unroll
    for (int e = 0; e < E_SZ; e++) acc += L[e] * wx[e * H_SZ + j];
    g_xin[t] = acc;
}

// -------- K1: sequential Elman recurrence (1 block, 1024 threads) ---------------
__global__ void k_recur(const float* __restrict__ wh, const float* __restrict__ h0) {
    __shared__ float hs[B_SZ * H_SZ];
    __shared__ float whs[H_SZ * H_SZ];
    int t = threadIdx.x, b = t >> 4, j = t & 15;
    if (t < H_SZ * H_SZ) whs[t] = wh[t];
    hs[t] = h0[t];
    __syncthreads();
    float xin = g_xin[t];
    for (int s = 0; s < S_LEN; s++) {
        float nxt = (s + 1 < S_LEN) ? g_xin[(s + 1) * (B_SZ * H_SZ) + t] : 0.f;
        float acc = xin;
#pragma unroll
        for (int k = 0; k < H_SZ; k++) acc += hs[b * H_SZ + k] * whs[k * H_SZ + j];
        float nh = tanhf(acc);
        __syncthreads();
        hs[t] = nh;
        g_h[s * (B_SZ * H_SZ) + t] = nh;
        xin = nxt;
        __syncthreads();
    }
}

// -------- K_wt: Wo [16,32000] f32 -> g_wt2 fragment-native bf16 layout ----------
// Column remap so D accumulators are contiguous: within group g, tile-col tc of
// tile 'tile' holds logical col  16g + 2*tc - (tc&1) + 2*tile.
// => thread lq's {d0[0],d0[1],d1[0],d1[1]} = logical cols 16g+4lq .. +3.
__global__ void k_wt(const float* __restrict__ wo) {
    int t = blockIdx.x * blockDim.x + threadIdx.x;
    int g = t >> 7, rem = t & 127;
    int lane = rem >> 2, r = rem & 3;
    int tc   = lane >> 2;                 // fragment n-column (0..7)
    int tile = r >> 1;
    int col  = g * 16 + 2 * tc - (tc & 1) + 2 * tile;
    int k0   = (lane & 3) * 2 + (r & 1) * 8;
    g_wt2[t] = packbf(wo[k0 * V_SZ + col], wo[(k0 + 1) * V_SZ + col]);
}

// -------- K2: HMMA logits GEMM + log-softmax ------------------------------------
// grid = (VSPLIT, NMT) = 1024 CTAs, 256 thr. PASS 0: sum(exp); PASS 1: store.
template <int PASS>
__global__ __launch_bounds__(256)
void k2(float* __restrict__ out) {
    int tid  = threadIdx.x;
    int w    = tid >> 5;
    int lane = tid & 31;
    int lq   = lane & 3;
    int bx   = blockIdx.x;             // vocab split
    int m0   = blockIdx.y * MT;
    int wr0  = m0 + w * 16;            // warp's 16-row tile base
    int rA   = lane >> 2;
    int kc   = lq * 2;

    // A fragment (loop-invariant). Pass 0: pre-scaled by log2(e) so exp = ex2.
    const float* hA = g_h + (long)(wr0 + rA) * H_SZ;
    const float* hB = g_h + (long)(wr0 + rA + 8) * H_SZ;
    float sc = (PASS == 0) ? LOG2E : 1.0f;
    uint32_t a[4];
    a[0] = packbf(sc * hA[kc],     sc * hA[kc + 1]);
    a[1] = packbf(sc * hB[kc],     sc * hB[kc + 1]);
    a[2] = packbf(sc * hA[kc + 8], sc * hA[kc + 9]);
    a[3] = packbf(sc * hB[kc + 8], sc * hB[kc + 9]);

    float lseA = 0.f, lseB = 0.f;
    if (PASS == 1) {
        const float4* pp = reinterpret_cast<const float4*>(g_ps + (long)(wr0 + rA) * VSPLIT);
        const float4* qq = reinterpret_cast<const float4*>(g_ps + (long)(wr0 + rA + 8) * VSPLIT);
        float sa = 0.f, sb = 0.f;
#pragma unroll
        for (int i = 0; i < VSPLIT / 4; i++) {
            float4 p = pp[i], q = qq[i];
            sa += (p.x + p.y) + (p.z + p.w);
            sb += (q.x + q.y) + (q.z + q.w);
        }
        lseA = logf(sa);
        lseB = logf(sb);
    }

    const uint4* bptr = reinterpret_cast<const uint4*>(g_wt2) + (long)bx * NG * 32 + lane;
    long orowA = (long)(wr0 + rA) * V_SZ + bx * VR + 4 * lq;
    long orowB = orowA + 8L * V_SZ;

    float psA = 0.f, psB = 0.f;

#pragma unroll 5
    for (int g = 0; g < NG; g++) {
        uint4 b = bptr[(long)g * 32];      // B frags for 16 cols (2 n-tiles)
        float d0[4], d1[4];
        mma16816(d0, a, b.x, b.y);
        mma16816(d1, a, b.z, b.w);
        if (PASS == 0) {
            psA += ex2(d0[0]) + ex2(d0[1]) + ex2(d1[0]) + ex2(d1[1]);
            psB += ex2(d0[2]) + ex2(d0[3]) + ex2(d1[2]) + ex2(d1[3]);
        } else {
            float4 vA = make_float4(d0[0] - lseA, d0[1] - lseA,
                                    d1[0] - lseA, d1[1] - lseA);
            float4 vB = make_float4(d0[2] - lseB, d0[3] - lseB,
                                    d1[2] - lseB, d1[3] - lseB);
            __stcs(reinterpret_cast<float4*>(out + orowA + g * 16), vA);
            __stcs(reinterpret_cast<float4*>(out + orowB + g * 16), vB);
        }
    }

    if (PASS == 0) {
        psA += __shfl_xor_sync(0xffffffffu, psA, 1);
        psA += __shfl_xor_sync(0xffffffffu, psA, 2);
        psB += __shfl_xor_sync(0xffffffffu, psB, 1);
        psB += __shfl_xor_sync(0xffffffffu, psB, 2);
        if (lq == 0) {
            g_ps[(long)(wr0 + rA) * VSPLIT + bx]     = psA;
            g_ps[(long)(wr0 + rA + 8) * VSPLIT + bx] = psB;
        }
    }
}

// -------- launch ----------------------------------------------------------------
extern "C" void kernel_launch(void* const* d_in, const int* in_sizes, int n_in,
                              void* d_out, int out_size) {
    const int*   input_batch = (const int*)d_in[0];
    const float* lookup      = (const float*)d_in[1];
    const float* weight_x    = (const float*)d_in[2];
    const float* weight_h    = (const float*)d_in[3];
    const float* weight_o    = (const float*)d_in[4];
    const float* h0          = (const float*)d_in[5];
    float*       out         = (float*)d_out;

    k_embed<<<(NROWS * H_SZ) / 256, 256>>>(input_batch, lookup, weight_x);
    k_wt<<<(V_SZ * H_SZ / 2) / 256, 256>>>(weight_o);
    k_recur<<<1, B_SZ * H_SZ>>>(weight_h, h0);
    dim3 g2(VSPLIT, NMT);
    k2<0><<<g2, 256>>>(out);
    k2<1><<<g2, 256>>>(out);
}

// round 9
// speedup vs baseline: 2.5028x; 1.0904x over previous
#include <cuda_runtime.h>
#include <cuda_bf16.h>
#include <cstdint>

#define S_LEN 128
#define B_SZ  64
#define V_SZ  32000
#define E_SZ  32
#define H_SZ  16
#define NROWS (S_LEN * B_SZ)   // 8192

#define MT     128             // rows per CTA (8 warps x 16 rows)
#define NMT    (NROWS / MT)    // 64
#define VSPLIT 16
#define VR     (V_SZ / VSPLIT) // 2000 cols per CTA
#define NG     (VR / 16)       // 125 col-groups (16 cols each)
#define NWT2   (V_SZ * H_SZ / 2)  // 256000 u32 in g_wt2

// -------- device scratch (allocation-free rule) --------------------------------
__device__ float    g_xin[NROWS * H_SZ];
__device__ float    g_h[NROWS * H_SZ];
__device__ uint32_t g_wt2[NWT2];              // Wo in MMA-B-fragment layout
__device__ float    g_ps[NROWS * VSPLIT];     // partial sum(exp) per (row, vsplit)

#define LOG2E 1.4426950408889634f

// -------- helpers ---------------------------------------------------------------
__device__ __forceinline__ uint32_t packbf(float lo, float hi) {
    __nv_bfloat162 p = __floats2bfloat162_rn(lo, hi);
    return *reinterpret_cast<uint32_t*>(&p);
}
__device__ __forceinline__ float ex2(float x) {
    float r;
    asm("ex2.approx.f32 %0, %1;" : "=f"(r) : "f"(x));
    return r;
}

__device__ __forceinline__ void mma16816(float d[4], const uint32_t a[4],
                                         uint32_t b0, uint32_t b1) {
    float z = 0.f;
    asm volatile(
        "mma.sync.aligned.m16n8k16.row.col.f32.bf16.bf16.f32 "
        "{%0,%1,%2,%3}, {%4,%5,%6,%7}, {%8,%9}, {%10,%11,%12,%13};"
        : "=f"(d[0]), "=f"(d[1]), "=f"(d[2]), "=f"(d[3])
        : "r"(a[0]), "r"(a[1]), "r"(a[2]), "r"(a[3]),
          "r"(b0), "r"(b1),
          "f"(z), "f"(z), "f"(z), "f"(z));
}

// -------- K0: xin = lookup[idx] @ Wx  (float4, 4 outputs/thread) ----------------
__global__ void k_embed(const int* __restrict__ idx,
                        const float* __restrict__ lookup,
                        const float* __restrict__ wx) {
    int t = blockIdx.x * blockDim.x + threadIdx.x;  // 32768 threads
    int row = t >> 2, j0 = (t & 3) * 4;
    const float* L = lookup + (long)idx[row] * E_SZ;
    float4 acc = make_float4(0.f, 0.f, 0.f, 0.f);
#pragma unroll
    for (int e = 0; e < E_SZ; e++) {
        float le = L[e];
        float4 w = *reinterpret_cast<const float4*>(wx + e * H_SZ + j0);
        acc.x += le * w.x; acc.y += le * w.y;
        acc.z += le * w.z; acc.w += le * w.w;
    }
    *reinterpret_cast<float4*>(g_xin + (long)row * H_SZ + j0) = acc;
}

// -------- K_prep: fused recurrence (blocks 0..31) + Wo repack (blocks 32..95) ---
// Recurrence: 1 warp per block, 2 batches per warp (16 lanes each), h exchanged
// via shfl -> zero barriers, 32 blocks run on 32 SMs in parallel with repack.
__global__ void k_prep(const float* __restrict__ wh,
                       const float* __restrict__ h0,
                       const float* __restrict__ wo) {
    int blk = blockIdx.x;
    if (blk < 32) {
        int tid = threadIdx.x;
        if (tid >= 32) return;
        int half = tid >> 4;          // which batch within the warp
        int j    = tid & 15;
        int bb   = blk * 2 + half;
        int base = bb * H_SZ + j;
        int src0 = half << 4;         // shfl source base lane

        float whr[H_SZ];
#pragma unroll
        for (int k = 0; k < H_SZ; k++) whr[k] = wh[k * H_SZ + j];

        float h   = h0[base];
        float xin = g_xin[base];
        for (int s = 0; s < S_LEN; s++) {
            float nxt = (s + 1 < S_LEN) ? g_xin[(s + 1) * (B_SZ * H_SZ) + base] : 0.f;
            float acc = xin;
#pragma unroll
            for (int k = 0; k < H_SZ; k++) {
                float hk = __shfl_sync(0xffffffffu, h, src0 | k);
                acc += hk * whr[k];
            }
            h = tanhf(acc);
            g_h[s * (B_SZ * H_SZ) + base] = h;
            xin = nxt;
        }
    } else {
        // Wo [16,32000] f32 -> g_wt2 fragment-native bf16 layout (remapped cols).
        // 64 blocks x 256 threads x 16 u32, vector stores.
        int t0 = ((blk - 32) * 256 + threadIdx.x) * 16;
        if (t0 >= NWT2) return;
        uint32_t v[16];
#pragma unroll
        for (int i = 0; i < 16; i++) {
            int t = t0 + i;
            int g = t >> 7, rem = t & 127;
            int lane = rem >> 2, r = rem & 3;
            int tc   = lane >> 2;
            int tile = r >> 1;
            int col  = g * 16 + 2 * tc - (tc & 1) + 2 * tile;
            int k0   = (lane & 3) * 2 + (r & 1) * 8;
            v[i] = packbf(wo[k0 * V_SZ + col], wo[(k0 + 1) * V_SZ + col]);
        }
        uint4* dst = reinterpret_cast<uint4*>(g_wt2 + t0);
#pragma unroll
        for (int i = 0; i < 4; i++)
            dst[i] = make_uint4(v[4 * i], v[4 * i + 1], v[4 * i + 2], v[4 * i + 3]);
    }
}

// -------- K2: HMMA logits GEMM + log-softmax ------------------------------------
// grid = (VSPLIT, NMT) = 1024 CTAs, 256 thr. PASS 0: sum(exp); PASS 1: store.
template <int PASS>
__global__ __launch_bounds__(256)
void k2(float* __restrict__ out) {
    int tid  = threadIdx.x;
    int w    = tid >> 5;
    int lane = tid & 31;
    int lq   = lane & 3;
    int bx   = blockIdx.x;             // vocab split
    int m0   = blockIdx.y * MT;
    int wr0  = m0 + w * 16;            // warp's 16-row tile base
    int rA   = lane >> 2;
    int kc   = lq * 2;

    // A fragment (loop-invariant). Pass 0: pre-scaled by log2(e) so exp = ex2.
    const float* hA = g_h + (long)(wr0 + rA) * H_SZ;
    const float* hB = g_h + (long)(wr0 + rA + 8) * H_SZ;
    float sc = (PASS == 0) ? LOG2E : 1.0f;
    uint32_t a[4];
    a[0] = packbf(sc * hA[kc],     sc * hA[kc + 1]);
    a[1] = packbf(sc * hB[kc],     sc * hB[kc + 1]);
    a[2] = packbf(sc * hA[kc + 8], sc * hA[kc + 9]);
    a[3] = packbf(sc * hB[kc + 8], sc * hB[kc + 9]);

    float lseA = 0.f, lseB = 0.f;
    if (PASS == 1) {
        const float4* pp = reinterpret_cast<const float4*>(g_ps + (long)(wr0 + rA) * VSPLIT);
        const float4* qq = reinterpret_cast<const float4*>(g_ps + (long)(wr0 + rA + 8) * VSPLIT);
        float sa = 0.f, sb = 0.f;
#pragma unroll
        for (int i = 0; i < VSPLIT / 4; i++) {
            float4 p = pp[i], q = qq[i];
            sa += (p.x + p.y) + (p.z + p.w);
            sb += (q.x + q.y) + (q.z + q.w);
        }
        lseA = logf(sa);
        lseB = logf(sb);
    }

    const uint4* bptr = reinterpret_cast<const uint4*>(g_wt2) + (long)bx * NG * 32 + lane;
    long orowA = (long)(wr0 + rA) * V_SZ + bx * VR + 4 * lq;
    long orowB = orowA + 8L * V_SZ;

    float psA = 0.f, psB = 0.f;

#pragma unroll 5
    for (int g = 0; g < NG; g++) {
        uint4 b = bptr[(long)g * 32];      // B frags for 16 cols (2 n-tiles)
        float d0[4], d1[4];
        mma16816(d0, a, b.x, b.y);
        mma16816(d1, a, b.z, b.w);
        if (PASS == 0) {
            psA += ex2(d0[0]) + ex2(d0[1]) + ex2(d1[0]) + ex2(d1[1]);
            psB += ex2(d0[2]) + ex2(d0[3]) + ex2(d1[2]) + ex2(d1[3]);
        } else {
            float4 vA = make_float4(d0[0] - lseA, d0[1] - lseA,
                                    d1[0] - lseA, d1[1] - lseA);
            float4 vB = make_float4(d0[2] - lseB, d0[3] - lseB,
                                    d1[2] - lseB, d1[3] - lseB);
            *reinterpret_cast<float4*>(out + orowA + g * 16) = vA;
            *reinterpret_cast<float4*>(out + orowB + g * 16) = vB;
        }
    }

    if (PASS == 0) {
        psA += __shfl_xor_sync(0xffffffffu, psA, 1);
        psA += __shfl_xor_sync(0xffffffffu, psA, 2);
        psB += __shfl_xor_sync(0xffffffffu, psB, 1);
        psB += __shfl_xor_sync(0xffffffffu, psB, 2);
        if (lq == 0) {
            g_ps[(long)(wr0 + rA) * VSPLIT + bx]     = psA;
            g_ps[(long)(wr0 + rA + 8) * VSPLIT + bx] = psB;
        }
    }
}

// -------- launch ----------------------------------------------------------------
extern "C" void kernel_launch(void* const* d_in, const int* in_sizes, int n_in,
                              void* d_out, int out_size) {
    const int*   input_batch = (const int*)d_in[0];
    const float* lookup      = (const float*)d_in[1];
    const float* weight_x    = (const float*)d_in[2];
    const float* weight_h    = (const float*)d_in[3];
    const float* weight_o    = (const float*)d_in[4];
    const float* h0          = (const float*)d_in[5];
    float*       out         = (float*)d_out;

    k_embed<<<(NROWS * H_SZ / 4) / 256, 256>>>(input_batch, lookup, weight_x);
    k_prep<<<96, 256>>>(weight_h, h0, weight_o);
    dim3 g2(VSPLIT, NMT);
    k2<0><<<g2, 256>>>(out);
    k2<1><<<g2, 256>>>(out);
}